// round 17
// baseline (speedup 1.0000x reference)
#include <cuda_runtime.h>
#include <cuda_bf16.h>
#include <cuda_fp8.h>
#include <cstdint>

// ============================================================================
// Simplicial attention, single-pass linearized, FP8 (e4m3) datapath.
// Per source (K=V):
//   Z_i = sum_{j != i} exp(s_ij)  (diag added EXACTLY in finalize for src0)
//   u_ij ~= (e_ij/Z_i) m_ij      (order-1; src0 diagonal exact via expm1)
//   out_i = sum_src (colsum(V) + T1_i/Z_i + u_ii v_i)/(M + t1_i/Z_i + u_ii)/3
// S and PV use mma.m16n8k32 e4m3; ALL fragments are plain LDS.32 (no ldmatrix):
//   S:  A = Q8[row][d]  (row-major),  B = K8[key][d]  (runs along d)
//   PV: A = U8[row][key](row-major),  B = VT8[d][key] (runs along key)
// 888-CTA wave-balanced grid; epilogue via global atomics (proven R14 path).
// ============================================================================

#define D      256
#define QR     64
#define KT     64
#define NT     64
#define NTH    256
#define NQ     8192
#define SCALE  0.0625f

#define NJOBS  57344
#define GRID   888

#define QLD8   272
#define KLD8   272
#define VLD8   80
#define ULD8   80

#define Q8_OFF 0
#define Q8_SZ  (64 * 272)                 // 17408
#define K8_OFF Q8_SZ
#define K8_SZ  (64 * 272)                 // x2
#define VT_OFF (K8_OFF + 2 * K8_SZ)       // 52224
#define VT_SZ  (256 * 80)                 // 20480 x2
#define U8_OFF (VT_OFF + 2 * VT_SZ)       // 93184
#define U8_SZ  (64 * 80)                  // 5120
#define SMEM_TOTAL (U8_OFF + U8_SZ)       // 98304 -> 2 CTAs/SM

// ---------------------------------------------------------------------------
__device__ __align__(128) uint8_t  g_kv8[28672L * 256];      // 7.3 MB fp8 [key][d]
__device__ __align__(128) uint8_t  g_kvT8[256L * 28672];     // 7.3 MB fp8 [d][key]
__device__ __align__(128) float    g_vsum[3 * 256];
__device__ __align__(128) uint32_t g_mb1[8192L * 128];       // B_low^T bits
__device__ __align__(128) float    g_T1[3L * 8192 * 256];    // 25 MB partials
__device__ __align__(128) float    g_Z[3 * 8192];
__device__ __align__(128) float    g_t1[3 * 8192];

__device__ __forceinline__ uint32_t smem_u32(const void* p) {
    return (uint32_t)__cvta_generic_to_shared(p);
}
__device__ __forceinline__ void cp16(uint32_t dst, const void* src) {
    asm volatile("cp.async.cg.shared.global [%0], [%1], 16;" :: "r"(dst), "l"(src));
}
#define CP_COMMIT() asm volatile("cp.async.commit_group;" ::: "memory")
#define CP_WAIT1()  asm volatile("cp.async.wait_group 1;" ::: "memory")

// fp8 mma: D(f32) += A(e4m3) * B(e4m3), m16n8k32
__device__ __forceinline__ void mma_fp8(float* d, uint32_t a0, uint32_t a1,
                                        uint32_t a2, uint32_t a3,
                                        uint32_t b0, uint32_t b1) {
    asm volatile(
        "mma.sync.aligned.m16n8k32.row.col.f32.e4m3.e4m3.f32 "
        "{%0,%1,%2,%3}, {%4,%5,%6,%7}, {%8,%9}, {%0,%1,%2,%3};\n"
        : "+f"(d[0]), "+f"(d[1]), "+f"(d[2]), "+f"(d[3])
        : "r"(a0), "r"(a1), "r"(a2), "r"(a3), "r"(b0), "r"(b1));
}

// ---------------------------------------------------------------------------
__global__ void init_kernel() {
    long idx = (long)blockIdx.x * 256 + threadIdx.x;
    if (idx < 3L * 8192 * 256) g_T1[idx] = 0.0f;
    if (idx < 3 * 8192) { g_Z[idx] = 0.0f; g_t1[idx] = 0.0f; }
    if (idx < 3 * 256) g_vsum[idx] = 0.0f;
}

__global__ void convert_kernel(const float* __restrict__ H,
                               const float* __restrict__ Hlow,
                               const float* __restrict__ Hhigh) {
    int r0 = blockIdx.x * 32, col = threadIdx.x;
    float acc = 0.0f;
    uint32_t wbuf[8];
    uint32_t w = 0;
    #pragma unroll 4
    for (int i = 0; i < 32; i++) {
        int r = r0 + i;
        float v;
        if (r < 8192)       v = H[(long)r * D + col];
        else if (r < 12288) v = Hlow[(long)(r - 8192) * D + col];
        else                v = Hhigh[(long)(r - 12288) * D + col];
        acc += v;
        uint8_t b = (uint8_t)__nv_cvt_float_to_fp8(v, __NV_SATFINITE, __NV_E4M3);
        g_kv8[(long)r * D + col] = b;
        w |= ((uint32_t)b) << (8 * (i & 3));
        if ((i & 3) == 3) { wbuf[i >> 2] = w; w = 0; }
    }
    uint4* dst = (uint4*)(g_kvT8 + (long)col * 28672 + r0);
    dst[0] = make_uint4(wbuf[0], wbuf[1], wbuf[2], wbuf[3]);
    dst[1] = make_uint4(wbuf[4], wbuf[5], wbuf[6], wbuf[7]);
    int src = (r0 < 8192) ? 0 : (r0 < 12288 ? 1 : 2);
    atomicAdd(&g_vsum[src * 256 + col], acc);
}

// pack B_low[4096][8192] transposed -> g_mb1[8192 rows][128 words]
__global__ void pack_T_kernel(const int* __restrict__ B) {
    __shared__ int sm[32 * 33];
    int kt = blockIdx.x & 127, it = blockIdx.x >> 7;
    int k0 = kt * 32, i0 = it * 32;
    int tid = threadIdx.x;
    #pragma unroll
    for (int s = 0; s < 4; s++) {
        int idx = tid + s * 256;
        int r = idx >> 5, c = idx & 31;
        sm[r * 33 + c] = B[(long)(k0 + r) * NQ + i0 + c];
    }
    __syncthreads();
    int w = tid >> 5, lane = tid & 31;
    #pragma unroll
    for (int q = 0; q < 4; q++) {
        int i = w * 4 + q;
        uint32_t word = __ballot_sync(0xffffffffu, sm[lane * 33 + i] != 0);
        if (lane == 0) g_mb1[(long)(i0 + i) * 128 + kt] = word;
    }
}

// ---------------------------------------------------------------------------
__global__ __launch_bounds__(NTH, 2)
void attn_kernel(const int* __restrict__ L,
                 const int* __restrict__ Bhigh) {
    extern __shared__ char smem[];
    uint32_t sb = smem_u32(smem);

    int tid = threadIdx.x, lane = tid & 31, w = tid >> 5;
    int mi = w & 3, ni = w >> 2;
    int g = lane >> 2, tig = lane & 3;
    int c2 = tig << 1;
    int m0 = mi * 16 + g;
    int wn = w * 32;

    int t    = (int)(((long)blockIdx.x * NJOBS) / GRID);
    int tend = (int)(((long)(blockIdx.x + 1) * NJOBS) / GRID);

    while (t < tend) {
        int qt = t / 448;
        int rem = t - qt * 448;
        int ch = rem >> 6;
        int j0 = rem & 63;
        int len = 64 - j0;
        if (len > tend - t) len = tend - t;
        int jEnd = j0 + len;
        int i0 = qt * QR;

        int src, kvrow0, kloc0, W;
        const int* mask;
        if (ch < 2)      { src = 0; kvrow0 = ch * 4096;            kloc0 = ch * 4096;     W = 8192;  mask = L; }
        else if (ch == 2){ src = 1; kvrow0 = 8192;                 kloc0 = 0;             W = 0;     mask = L; }
        else             { src = 2; kvrow0 = 12288 + (ch-3)*4096;  kloc0 = (ch-3)*4096;   W = 16384; mask = Bhigh; }
        int diag_j = -1;
        if (src == 0) { int dj = (i0 - kloc0) >> 6; if (dj >= 0 && dj < NT) diag_j = dj; }

        // ---- prologue: Q8 + (K8,VT8)(j0) group, (K8,VT8)(j0+1) group
        {
            const uint8_t* gq = g_kv8 + (long)i0 * D;
            #pragma unroll
            for (int i = 0; i < 4; i++) {
                int idx = tid + i * NTH;                 // 1024 chunks
                int r = idx >> 4, c = (idx & 15) << 4;
                cp16(sb + Q8_OFF + (uint32_t)(r * QLD8 + c), gq + (long)r * D + c);
            }
            const uint8_t* gk = g_kv8 + (long)(kvrow0 + j0 * KT) * D;
            uint32_t kdst = sb + K8_OFF + (uint32_t)(j0 & 1) * K8_SZ;
            #pragma unroll
            for (int i = 0; i < 4; i++) {
                int idx = tid + i * NTH;
                int r = idx >> 4, c = (idx & 15) << 4;
                cp16(kdst + (uint32_t)(r * KLD8 + c), gk + (long)r * D + c);
            }
            const uint8_t* gv = g_kvT8 + (kvrow0 + j0 * KT);
            uint32_t vdst = sb + VT_OFF + (uint32_t)(j0 & 1) * VT_SZ;
            #pragma unroll
            for (int i = 0; i < 4; i++) {
                int idx = tid + i * NTH;
                int r = idx >> 2, c = (idx & 3) << 4;
                cp16(vdst + (uint32_t)(r * VLD8 + c), gv + (long)r * 28672 + c);
            }
            CP_COMMIT();
            if (len > 1) {
                const uint8_t* gk1 = g_kv8 + (long)(kvrow0 + (j0 + 1) * KT) * D;
                uint32_t kdst1 = sb + K8_OFF + (uint32_t)((j0 + 1) & 1) * K8_SZ;
                #pragma unroll
                for (int i = 0; i < 4; i++) {
                    int idx = tid + i * NTH;
                    int r = idx >> 4, c = (idx & 15) << 4;
                    cp16(kdst1 + (uint32_t)(r * KLD8 + c), gk1 + (long)r * D + c);
                }
                const uint8_t* gv1 = g_kvT8 + (kvrow0 + (j0 + 1) * KT);
                uint32_t vdst1 = sb + VT_OFF + (uint32_t)((j0 + 1) & 1) * VT_SZ;
                #pragma unroll
                for (int i = 0; i < 4; i++) {
                    int idx = tid + i * NTH;
                    int r = idx >> 2, c = (idx & 3) << 4;
                    cp16(vdst1 + (uint32_t)(r * VLD8 + c), gv1 + (long)r * 28672 + c);
                }
            }
            CP_COMMIT();
        }

        float zacc0 = 0.f, zacc1 = 0.f, t1acc0 = 0.f, t1acc1 = 0.f;
        float acc[16][4];
        #pragma unroll
        for (int f = 0; f < 16; f++) { acc[f][0]=0.f; acc[f][1]=0.f; acc[f][2]=0.f; acc[f][3]=0.f; }

        const int* mr0 = mask + (long)(i0 + m0) * W + kloc0 + ni * 32 + c2;
        const int* mr1 = mask + (long)(i0 + m0 + 8) * W + kloc0 + ni * 32 + c2;
        const uint32_t* br0 = g_mb1 + (long)(i0 + m0) * 128;
        const uint32_t* br1 = g_mb1 + (long)(i0 + m0 + 8) * 128;

        for (int j = j0; j < jEnd; j++) {
            CP_WAIT1();
            __syncthreads();
            const char* k8 = smem + K8_OFF + (j & 1) * K8_SZ;
            const char* vt = smem + VT_OFF + (j & 1) * VT_SZ;
            const char* q8 = smem + Q8_OFF;
            char* u8 = smem + U8_OFF;

            // ---- mask loads (early; overlap S-GEMM)
            int2 ma[4], mb[4];
            uint64_t bt0 = 0, bt1 = 0;
            if (src == 1) {
                bt0 = *(const uint64_t*)(br0 + j * 2);
                bt1 = *(const uint64_t*)(br1 + j * 2);
            } else {
                #pragma unroll
                for (int f = 0; f < 4; f++) {
                    ma[f] = *(const int2*)(mr0 + j * 64 + f * 8);
                    mb[f] = *(const int2*)(mr1 + j * 64 + f * 8);
                }
            }

            // ---- S = Q K^T (64x64) fp8: warp tile m16 x n32
            float d[4][4];
            #pragma unroll
            for (int f = 0; f < 4; f++) { d[f][0]=0.f; d[f][1]=0.f; d[f][2]=0.f; d[f][3]=0.f; }
            #pragma unroll
            for (int kk = 0; kk < 8; kk++) {
                int ko = kk * 32 + 4 * tig;
                uint32_t a0 = *(const uint32_t*)(q8 + (mi*16 + g) * QLD8 + ko);
                uint32_t a1 = *(const uint32_t*)(q8 + (mi*16 + g + 8) * QLD8 + ko);
                uint32_t a2 = *(const uint32_t*)(q8 + (mi*16 + g) * QLD8 + ko + 16);
                uint32_t a3 = *(const uint32_t*)(q8 + (mi*16 + g + 8) * QLD8 + ko + 16);
                #pragma unroll
                for (int nb = 0; nb < 4; nb++) {
                    int key = ni * 32 + nb * 8 + g;
                    uint32_t b0 = *(const uint32_t*)(k8 + key * KLD8 + ko);
                    uint32_t b1 = *(const uint32_t*)(k8 + key * KLD8 + ko + 16);
                    mma_fp8(d[nb], a0, a1, a2, a3, b0, b1);
                }
            }

            // ---- e = exp(s*scale); w = e*mask; diag excluded from Z (exact in finalize)
            bool diagTile = (j == diag_j);
            #pragma unroll
            for (int f = 0; f < 4; f++) {
                int n = ni * 32 + f * 8 + c2;
                float e0 = __expf(d[f][0] * SCALE);
                float e1 = __expf(d[f][1] * SCALE);
                float e2 = __expf(d[f][2] * SCALE);
                float e3 = __expf(d[f][3] * SCALE);
                zacc0 += e0 + e1;
                zacc1 += e2 + e3;
                bool b00, b01, b10, b11;
                if (src == 1) {
                    b00 = (bt0 >> n) & 1;  b01 = (bt0 >> (n + 1)) & 1;
                    b10 = (bt1 >> n) & 1;  b11 = (bt1 >> (n + 1)) & 1;
                } else {
                    b00 = ma[f].x != 0;  b01 = ma[f].y != 0;
                    b10 = mb[f].x != 0;  b11 = mb[f].y != 0;
                }
                if (diagTile) {
                    if (m0 == n)         { zacc0 -= e0; b00 = false; }
                    if (m0 == n + 1)     { zacc0 -= e1; b01 = false; }
                    if (m0 + 8 == n)     { zacc1 -= e2; b10 = false; }
                    if (m0 + 8 == n + 1) { zacc1 -= e3; b11 = false; }
                }
                float w0 = b00 ? e0 : 0.f, w1 = b01 ? e1 : 0.f;
                float w2 = b10 ? e2 : 0.f, w3 = b11 ? e3 : 0.f;
                t1acc0 += w0 + w1;
                t1acc1 += w2 + w3;
                uint16_t p0, p1;
                asm("cvt.rn.satfinite.e4m3x2.f32 %0, %1, %2;" : "=h"(p0) : "f"(w1), "f"(w0));
                asm("cvt.rn.satfinite.e4m3x2.f32 %0, %1, %2;" : "=h"(p1) : "f"(w3), "f"(w2));
                *(uint16_t*)(u8 + m0 * ULD8 + n)       = p0;
                *(uint16_t*)(u8 + (m0 + 8) * ULD8 + n) = p1;
            }
            __syncthreads();

            // ---- T1 += W @ V fp8: warp owns all 64 rows x 32 d-cols
            #pragma unroll
            for (int kk = 0; kk < 2; kk++) {
                int ko = kk * 32 + 4 * tig;
                uint32_t bv[4][2];
                #pragma unroll
                for (int nb = 0; nb < 4; nb++) {
                    int dcol = wn + nb * 8 + g;
                    bv[nb][0] = *(const uint32_t*)(vt + dcol * VLD8 + ko);
                    bv[nb][1] = *(const uint32_t*)(vt + dcol * VLD8 + ko + 16);
                }
                #pragma unroll
                for (int ms = 0; ms < 4; ms++) {
                    uint32_t a0 = *(const uint32_t*)(u8 + (ms*16 + g) * ULD8 + ko);
                    uint32_t a1 = *(const uint32_t*)(u8 + (ms*16 + g + 8) * ULD8 + ko);
                    uint32_t a2 = *(const uint32_t*)(u8 + (ms*16 + g) * ULD8 + ko + 16);
                    uint32_t a3 = *(const uint32_t*)(u8 + (ms*16 + g + 8) * ULD8 + ko + 16);
                    #pragma unroll
                    for (int nb = 0; nb < 4; nb++)
                        mma_fp8(acc[ms * 4 + nb], a0, a1, a2, a3, bv[nb][0], bv[nb][1]);
                }
            }
            __syncthreads();

            // ---- refill buffers (j&1) with tile j+2
            if (j + 2 < jEnd) {
                const uint8_t* gk = g_kv8 + (long)(kvrow0 + (j + 2) * KT) * D;
                uint32_t kdst = sb + K8_OFF + (uint32_t)(j & 1) * K8_SZ;
                #pragma unroll
                for (int i = 0; i < 4; i++) {
                    int idx = tid + i * NTH;
                    int r = idx >> 4, c = (idx & 15) << 4;
                    cp16(kdst + (uint32_t)(r * KLD8 + c), gk + (long)r * D + c);
                }
                const uint8_t* gv = g_kvT8 + (kvrow0 + (j + 2) * KT);
                uint32_t vdst = sb + VT_OFF + (uint32_t)(j & 1) * VT_SZ;
                #pragma unroll
                for (int i = 0; i < 4; i++) {
                    int idx = tid + i * NTH;
                    int r = idx >> 2, c = (idx & 3) << 4;
                    cp16(vdst + (uint32_t)(r * VLD8 + c), gv + (long)r * 28672 + c);
                }
            }
            CP_COMMIT();
        }

        // ---- row partials: Z and t1
        zacc0 += __shfl_xor_sync(~0u, zacc0, 1); zacc0 += __shfl_xor_sync(~0u, zacc0, 2);
        zacc1 += __shfl_xor_sync(~0u, zacc1, 1); zacc1 += __shfl_xor_sync(~0u, zacc1, 2);
        t1acc0 += __shfl_xor_sync(~0u, t1acc0, 1); t1acc0 += __shfl_xor_sync(~0u, t1acc0, 2);
        t1acc1 += __shfl_xor_sync(~0u, t1acc1, 1); t1acc1 += __shfl_xor_sync(~0u, t1acc1, 2);
        if (tig == 0) {
            atomicAdd(&g_Z[src * 8192 + i0 + m0],      zacc0);
            atomicAdd(&g_Z[src * 8192 + i0 + m0 + 8],  zacc1);
            atomicAdd(&g_t1[src * 8192 + i0 + m0],     t1acc0);
            atomicAdd(&g_t1[src * 8192 + i0 + m0 + 8], t1acc1);
        }

        // ---- T1 partial atomics (unscaled; finalize applies 1/Z)
        #pragma unroll
        for (int ms = 0; ms < 4; ms++) {
            long b0 = ((long)src * 8192 + i0 + ms * 16 + g) * 256;
            #pragma unroll
            for (int f = 0; f < 4; f++) {
                int col = wn + f * 8 + c2;
                float* ac = acc[ms * 4 + f];
                atomicAdd(&g_T1[b0 + col],               ac[0]);
                atomicAdd(&g_T1[b0 + col + 1],           ac[1]);
                atomicAdd(&g_T1[b0 + 8 * 256 + col],     ac[2]);
                atomicAdd(&g_T1[b0 + 8 * 256 + col + 1], ac[3]);
            }
        }

        t += len;
        __syncthreads();
    }
}

// ---------------------------------------------------------------------------
__global__ void finalize_kernel(const float* __restrict__ H,
                                const int* __restrict__ L,
                                float* __restrict__ out) {
    __shared__ float red[256];
    int i = blockIdx.x, c = threadIdx.x;
    float v = H[(long)i * 256 + c];
    red[c] = v * v;
    __syncthreads();
    #pragma unroll
    for (int s = 128; s > 0; s >>= 1) {
        if (c < s) red[c] += red[c + s];
        __syncthreads();
    }
    float sii = red[0];
    float eii = __expf(sii * SCALE);          // exact diag (fp32 H)
    float Z0 = g_Z[i] + eii;
    float rz0 = 1.0f / Z0;
    float rz1 = 1.0f / g_Z[8192 + i];
    float rz2 = 1.0f / g_Z[16384 + i];

    bool mii = L[(long)i * NQ + i] != 0;
    float u = mii ? (__expf(eii * rz0) - 1.0f) : 0.0f;

    float n0 = g_vsum[c]       + g_T1[((long)0 * 8192 + i) * 256 + c] * rz0 + u * v;
    float d0 = 8192.0f  + g_t1[i] * rz0 + u;
    float n1 = g_vsum[256 + c] + g_T1[((long)1 * 8192 + i) * 256 + c] * rz1;
    float d1 = 4096.0f  + g_t1[8192 + i] * rz1;
    float n2 = g_vsum[512 + c] + g_T1[((long)2 * 8192 + i) * 256 + c] * rz2;
    float d2 = 16384.0f + g_t1[16384 + i] * rz2;

    out[(long)i * 256 + c] = (n0 / d0 + n1 / d1 + n2 / d2) * (1.0f / 3.0f);
}

// ---------------------------------------------------------------------------
extern "C" void kernel_launch(void* const* d_in, const int* in_sizes, int n_in,
                              void* d_out, int out_size) {
    const int*   L     = (const int*)d_in[0];
    const float* H     = (const float*)d_in[1];
    const int*   Blow  = (const int*)d_in[2];
    const float* Hlow  = (const float*)d_in[3];
    const int*   Bhigh = (const int*)d_in[4];
    const float* Hhigh = (const float*)d_in[5];
    float* out = (float*)d_out;

    cudaFuncSetAttribute(attn_kernel,
                         cudaFuncAttributeMaxDynamicSharedMemorySize, SMEM_TOTAL);

    init_kernel<<<24576, 256>>>();
    convert_kernel<<<896, 256>>>(H, Hlow, Hhigh);
    pack_T_kernel<<<32768, 256>>>(Blow);
    attn_kernel<<<GRID, NTH, SMEM_TOTAL>>>(L, Bhigh);
    finalize_kernel<<<8192, 256>>>(H, L, out);
}